// round 16
// baseline (speedup 1.0000x reference)
#include <cuda_runtime.h>

#define FULLMASK 0xffffffffu
typedef unsigned long long ull;

// ---------- packed f32x2 helpers (Blackwell sm_103a) ----------
__device__ __forceinline__ ull pk2(float a, float b) {
    ull r;
    asm("mov.b64 %0, {%1, %2};" : "=l"(r) : "f"(a), "f"(b));
    return r;
}
__device__ __forceinline__ float2 upk2(ull v) {
    float2 r;
    asm("mov.b64 {%0, %1}, %2;" : "=f"(r.x), "=f"(r.y) : "l"(v));
    return r;
}
__device__ __forceinline__ ull dup2(float a) { return pk2(a, a); }

__device__ __forceinline__ ull ffma2(ull a, ull b, ull c) {
    ull d;
    asm("fma.rn.f32x2 %0, %1, %2, %3;" : "=l"(d) : "l"(a), "l"(b), "l"(c));
    return d;
}
__device__ __forceinline__ ull add2(ull a, ull b) {
    ull d;
    asm("add.rn.f32x2 %0, %1, %2;" : "=l"(d) : "l"(a), "l"(b));
    return d;
}

// HW tanh: single MUFU.TANH (sm_75+), abs err ~1e-5
__device__ __forceinline__ float tanh_hw(float z) {
    float r;
    asm("tanh.approx.f32 %0, %1;" : "=f"(r) : "f"(z));
    return r;
}

// float->int via magic number (valid |v| < 2^22): FADD + IADD, replaces F2I cvt
#define MAGIC_F 12582912.0f          // 1.5 * 2^23
__device__ __forceinline__ int f2i_magic(float v) {
    return __float_as_int(v + MAGIC_F) - __float_as_int(MAGIC_F);
}

// warp sum of 2^23-scaled values: magic f2i -> redux.s32 -> cvt back
__device__ __forceinline__ float redux_scaled(float gp_scaled) {
    int si;
    const int gi = f2i_magic(gp_scaled);
    asm("redux.sync.add.s32 %0, %1, 0xffffffff;" : "=r"(si) : "r"(gi));
    float sf;
    asm("cvt.rn.f32.s32 %0, %1;" : "=f"(sf) : "r"(si));
    return sf;
}

// ONE element per warp, 2048 single-warp CTAs, TRUE single wave:
// register budget cut to ~115 by splitting W2 — column jA in 64 regs,
// column jB in per-CTA SMEM (lane-sliced, conflict-free LDS.128).
// 14 CTAs/SM resident -> 3.46 warps/SMSP (2x R15), per-warp work halved.
// Tail: HW tanh, magic-f2i + redux.s32, off-chain dtn folds.
__global__ void __launch_bounds__(32, 14)
maxwell_ffnn_kernel(const float* __restrict__ x,
                    const float* __restrict__ W1,
                    const float* __restrict__ b1,
                    const float* __restrict__ W2,
                    const float* __restrict__ b2,
                    const float* __restrict__ W3,
                    const float* __restrict__ b3,
                    float* __restrict__ out) {
    __shared__ __align__(16) ull hbuf[2][32];            // [parity][lane]
    __shared__ __align__(16) ulonglong2 w2BS[16][32];    // [k][lane]: rows 4k..4k+3, col jB

    const int l  = threadIdx.x & 31;
    const int jA = l;
    const int jB = l + 32;
    const int u0 = 2 * l;

    const float SC = 8388608.0f;               // 2^23 (redux scale)
    const float IS = 1.1920928955078125e-7f;   // 2^-23

    // ---- loop-invariant weights ----
    const ull c1a = pk2(__ldg(&W1[u0]),      __ldg(&W1[u0 + 1]));
    const ull c1b = pk2(__ldg(&W1[64 + u0]), __ldg(&W1[64 + u0 + 1]));
    const ull cb1 = pk2(__ldg(&b1[u0]),      __ldg(&b1[u0 + 1]));

    // column jA: 32 row-pair packed regs (64 registers)
    ull w2A[32];
#pragma unroll
    for (int s = 0; s < 32; ++s)
        w2A[s] = pk2(__ldg(&W2[(2 * s) * 64 + jA]),
                     __ldg(&W2[(2 * s + 1) * 64 + jA]));

    // column jB: staged to SMEM (each lane owns its column slice)
#pragma unroll
    for (int k = 0; k < 16; ++k) {
        const ull p0 = pk2(__ldg(&W2[(4 * k) * 64 + jB]),
                           __ldg(&W2[(4 * k + 1) * 64 + jB]));
        const ull p1 = pk2(__ldg(&W2[(4 * k + 2) * 64 + jB]),
                           __ldg(&W2[(4 * k + 3) * 64 + jB]));
        w2BS[k][l] = make_ulonglong2(p0, p1);
    }
    __syncwarp();

    const float b2A = __ldg(&b2[jA]);
    const float b2B = __ldg(&b2[jB]);
    const float w3A = SC * __ldg(&W3[jA]);     // 2^23 * W3
    const float w3B = SC * __ldg(&W3[jB]);
    const float b3v = __ldg(&b3[0]);

    const float2* xp = (const float2*)(x + (size_t)blockIdx.x * 2048);
    float* op = out + (size_t)blockIdx.x * 1024;

    float gamma = 0.0f;
    float2 xv = __ldg(&xp[0]);
    const ull zero2 = pk2(0.0f, 0.0f);

#pragma unroll 2
    for (int t = 0; t < 1024; ++t) {
        const int par = t & 1;
        const float eps = xv.x, dtn = xv.y;
        if (t < 1023) xv = __ldg(&xp[t + 1]);   // prefetch

        // off-chain folds
        const float gpre = fmaf(dtn, b3v, gamma);   // gamma + dtn*b3
        const float dIS  = dtn * IS;                // dtn * 2^-23

        // ---- layer 1: my 2 units (1x ffma2 chain + 2 MUFU.TANH) ----
        {
            const ull p = ffma2(dup2(gamma), c1b, ffma2(dup2(eps), c1a, cb1));
            const float2 q = upk2(p);
            hbuf[par][l] = pk2(tanh_hw(q.x), tanh_hw(q.y));
        }
        __syncwarp();

        // ---- layer 2: cols jA (regs) + jB (SMEM), 8 chains depth 8 ----
        ull A0 = pk2(b2A, 0.0f), A1 = zero2, A2 = zero2, A3 = zero2;
        ull B0 = pk2(b2B, 0.0f), B1 = zero2, B2 = zero2, B3 = zero2;
        {
            const ulonglong2* hp = (const ulonglong2*)&hbuf[par][0];
#pragma unroll
            for (int k = 0; k < 8; ++k) {
                const ulonglong2 ha  = hp[2 * k];          // h pairs 4k, 4k+1
                const ulonglong2 hb  = hp[2 * k + 1];      // h pairs 4k+2, 4k+3
                const ulonglong2 wb0 = w2BS[2 * k][l];     // col B rows 8k..8k+3
                const ulonglong2 wb1 = w2BS[2 * k + 1][l]; // col B rows 8k+4..8k+7
                A0 = ffma2(ha.x, w2A[4 * k],     A0);
                B0 = ffma2(ha.x, wb0.x,          B0);
                A1 = ffma2(ha.y, w2A[4 * k + 1], A1);
                B1 = ffma2(ha.y, wb0.y,          B1);
                A2 = ffma2(hb.x, w2A[4 * k + 2], A2);
                B2 = ffma2(hb.x, wb1.x,          B2);
                A3 = ffma2(hb.y, w2A[4 * k + 3], A3);
                B3 = ffma2(hb.y, wb1.y,          B3);
            }
        }
        const float2 aA = upk2(add2(add2(A0, A1), add2(A2, A3)));
        const float2 aB = upk2(add2(add2(B0, B1), add2(B2, B3)));
        const float gp = fmaf(tanh_hw(aA.x + aA.y), w3A,
                              tanh_hw(aB.x + aB.y) * w3B);

        // ---- warp sum (single redux) + gamma update ----
        const float s = redux_scaled(gp);
        gamma = fmaf(dIS, s, gpre);

        // sigma = 0.5*eps + 2*(eps - gamma) = 2.5*eps - 2*gamma
        if (l == 0) op[t] = fmaf(-2.0f, gamma, 2.5f * eps);
    }
}

extern "C" void kernel_launch(void* const* d_in, const int* in_sizes, int n_in,
                              void* d_out, int out_size) {
    (void)in_sizes; (void)n_in; (void)out_size;
    const float* x  = (const float*)d_in[0];
    const float* W1 = (const float*)d_in[1];
    const float* b1 = (const float*)d_in[2];
    const float* W2 = (const float*)d_in[3];
    const float* b2 = (const float*)d_in[4];
    const float* W3 = (const float*)d_in[5];
    const float* b3 = (const float*)d_in[6];
    float* out = (float*)d_out;

    // 1 element per warp: 2048 single-warp CTAs, 14/SM resident, single wave
    maxwell_ffnn_kernel<<<2048, 32>>>(x, W1, b1, W2, b2, W3, b3, out);
}

// round 17
// speedup vs baseline: 1.0017x; 1.0017x over previous
#include <cuda_runtime.h>

#define FULLMASK 0xffffffffu
typedef unsigned long long ull;

// ---------- packed f32x2 helpers (Blackwell sm_103a) ----------
__device__ __forceinline__ ull pk2(float a, float b) {
    ull r;
    asm("mov.b64 %0, {%1, %2};" : "=l"(r) : "f"(a), "f"(b));
    return r;
}
__device__ __forceinline__ float2 upk2(ull v) {
    float2 r;
    asm("mov.b64 {%0, %1}, %2;" : "=f"(r.x), "=f"(r.y) : "l"(v));
    return r;
}
__device__ __forceinline__ ull dup2(float a) { return pk2(a, a); }

__device__ __forceinline__ ull ffma2(ull a, ull b, ull c) {
    ull d;
    asm("fma.rn.f32x2 %0, %1, %2, %3;" : "=l"(d) : "l"(a), "l"(b), "l"(c));
    return d;
}
__device__ __forceinline__ ull add2(ull a, ull b) {
    ull d;
    asm("add.rn.f32x2 %0, %1, %2;" : "=l"(d) : "l"(a), "l"(b));
    return d;
}

// HW tanh: single MUFU.TANH (sm_75+), abs err ~1e-5
__device__ __forceinline__ float tanh_hw(float z) {
    float r;
    asm("tanh.approx.f32 %0, %1;" : "=f"(r) : "f"(z));
    return r;
}

// float->int via magic number (valid |v| < 2^22): FADD + IADD, replaces F2I cvt
#define MAGIC_F 12582912.0f          // 1.5 * 2^23
__device__ __forceinline__ int f2i_magic(float v) {
    return __float_as_int(v + MAGIC_F) - __float_as_int(MAGIC_F);
}

// warp sum of 2^23-scaled values: magic f2i -> redux.s32 -> cvt back
__device__ __forceinline__ float redux_scaled(float gp_scaled) {
    int si;
    const int gi = f2i_magic(gp_scaled);
    asm("redux.sync.add.s32 %0, %1, 0xffffffff;" : "=r"(si) : "r"(gi));
    float sf;
    asm("cvt.rn.f32.s32 %0, %1;" : "=f"(sf) : "r"(si));
    return sf;
}

// ONE element per warp, 2048 single-warp CTAs, TRUE single wave:
// register budget cut to ~115 by splitting W2 — column jA in 64 regs,
// column jB in per-CTA SMEM (lane-sliced, conflict-free LDS.128).
// 14 CTAs/SM resident -> 3.46 warps/SMSP (2x R15), per-warp work halved.
// Tail: HW tanh, magic-f2i + redux.s32, off-chain dtn folds.
__global__ void __launch_bounds__(32, 14)
maxwell_ffnn_kernel(const float* __restrict__ x,
                    const float* __restrict__ W1,
                    const float* __restrict__ b1,
                    const float* __restrict__ W2,
                    const float* __restrict__ b2,
                    const float* __restrict__ W3,
                    const float* __restrict__ b3,
                    float* __restrict__ out) {
    __shared__ __align__(16) ull hbuf[2][32];            // [parity][lane]
    __shared__ __align__(16) ulonglong2 w2BS[16][32];    // [k][lane]: rows 4k..4k+3, col jB

    const int l  = threadIdx.x & 31;
    const int jA = l;
    const int jB = l + 32;
    const int u0 = 2 * l;

    const float SC = 8388608.0f;               // 2^23 (redux scale)
    const float IS = 1.1920928955078125e-7f;   // 2^-23

    // ---- loop-invariant weights ----
    const ull c1a = pk2(__ldg(&W1[u0]),      __ldg(&W1[u0 + 1]));
    const ull c1b = pk2(__ldg(&W1[64 + u0]), __ldg(&W1[64 + u0 + 1]));
    const ull cb1 = pk2(__ldg(&b1[u0]),      __ldg(&b1[u0 + 1]));

    // column jA: 32 row-pair packed regs (64 registers)
    ull w2A[32];
#pragma unroll
    for (int s = 0; s < 32; ++s)
        w2A[s] = pk2(__ldg(&W2[(2 * s) * 64 + jA]),
                     __ldg(&W2[(2 * s + 1) * 64 + jA]));

    // column jB: staged to SMEM (each lane owns its column slice)
#pragma unroll
    for (int k = 0; k < 16; ++k) {
        const ull p0 = pk2(__ldg(&W2[(4 * k) * 64 + jB]),
                           __ldg(&W2[(4 * k + 1) * 64 + jB]));
        const ull p1 = pk2(__ldg(&W2[(4 * k + 2) * 64 + jB]),
                           __ldg(&W2[(4 * k + 3) * 64 + jB]));
        w2BS[k][l] = make_ulonglong2(p0, p1);
    }
    __syncwarp();

    const float b2A = __ldg(&b2[jA]);
    const float b2B = __ldg(&b2[jB]);
    const float w3A = SC * __ldg(&W3[jA]);     // 2^23 * W3
    const float w3B = SC * __ldg(&W3[jB]);
    const float b3v = __ldg(&b3[0]);

    const float2* xp = (const float2*)(x + (size_t)blockIdx.x * 2048);
    float* op = out + (size_t)blockIdx.x * 1024;

    float gamma = 0.0f;
    float2 xv = __ldg(&xp[0]);
    const ull zero2 = pk2(0.0f, 0.0f);

#pragma unroll 2
    for (int t = 0; t < 1024; ++t) {
        const int par = t & 1;
        const float eps = xv.x, dtn = xv.y;
        if (t < 1023) xv = __ldg(&xp[t + 1]);   // prefetch

        // off-chain folds
        const float gpre = fmaf(dtn, b3v, gamma);   // gamma + dtn*b3
        const float dIS  = dtn * IS;                // dtn * 2^-23

        // ---- layer 1: my 2 units (1x ffma2 chain + 2 MUFU.TANH) ----
        {
            const ull p = ffma2(dup2(gamma), c1b, ffma2(dup2(eps), c1a, cb1));
            const float2 q = upk2(p);
            hbuf[par][l] = pk2(tanh_hw(q.x), tanh_hw(q.y));
        }
        __syncwarp();

        // ---- layer 2: cols jA (regs) + jB (SMEM), 8 chains depth 8 ----
        ull A0 = pk2(b2A, 0.0f), A1 = zero2, A2 = zero2, A3 = zero2;
        ull B0 = pk2(b2B, 0.0f), B1 = zero2, B2 = zero2, B3 = zero2;
        {
            const ulonglong2* hp = (const ulonglong2*)&hbuf[par][0];
#pragma unroll
            for (int k = 0; k < 8; ++k) {
                const ulonglong2 ha  = hp[2 * k];          // h pairs 4k, 4k+1
                const ulonglong2 hb  = hp[2 * k + 1];      // h pairs 4k+2, 4k+3
                const ulonglong2 wb0 = w2BS[2 * k][l];     // col B rows 8k..8k+3
                const ulonglong2 wb1 = w2BS[2 * k + 1][l]; // col B rows 8k+4..8k+7
                A0 = ffma2(ha.x, w2A[4 * k],     A0);
                B0 = ffma2(ha.x, wb0.x,          B0);
                A1 = ffma2(ha.y, w2A[4 * k + 1], A1);
                B1 = ffma2(ha.y, wb0.y,          B1);
                A2 = ffma2(hb.x, w2A[4 * k + 2], A2);
                B2 = ffma2(hb.x, wb1.x,          B2);
                A3 = ffma2(hb.y, w2A[4 * k + 3], A3);
                B3 = ffma2(hb.y, wb1.y,          B3);
            }
        }
        const float2 aA = upk2(add2(add2(A0, A1), add2(A2, A3)));
        const float2 aB = upk2(add2(add2(B0, B1), add2(B2, B3)));
        const float gp = fmaf(tanh_hw(aA.x + aA.y), w3A,
                              tanh_hw(aB.x + aB.y) * w3B);

        // ---- warp sum (single redux) + gamma update ----
        const float s = redux_scaled(gp);
        gamma = fmaf(dIS, s, gpre);

        // sigma = 0.5*eps + 2*(eps - gamma) = 2.5*eps - 2*gamma
        if (l == 0) op[t] = fmaf(-2.0f, gamma, 2.5f * eps);
    }
}

extern "C" void kernel_launch(void* const* d_in, const int* in_sizes, int n_in,
                              void* d_out, int out_size) {
    (void)in_sizes; (void)n_in; (void)out_size;
    const float* x  = (const float*)d_in[0];
    const float* W1 = (const float*)d_in[1];
    const float* b1 = (const float*)d_in[2];
    const float* W2 = (const float*)d_in[3];
    const float* b2 = (const float*)d_in[4];
    const float* W3 = (const float*)d_in[5];
    const float* b3 = (const float*)d_in[6];
    float* out = (float*)d_out;

    // 1 element per warp: 2048 single-warp CTAs, 14/SM resident, single wave
    maxwell_ffnn_kernel<<<2048, 32>>>(x, W1, b1, W2, b2, W3, b3, out);
}